// round 15
// baseline (speedup 1.0000x reference)
#include <cuda_runtime.h>
#include <math.h>

// ---------------------------------------------------------------------------
// Constants fixed by setup_inputs
// ---------------------------------------------------------------------------
#define NF      32
#define XS      576        // 2*9*32 floats per node
#define NNODE   1024
#define NMOL    32
#define NATOM   32
#define EPM     992
#define NEDGE   31744

// ---------------------------------------------------------------------------
// Compile-time Clebsch-Gordan per-entry evaluation (replicates _build_cg).
// ---------------------------------------------------------------------------
namespace cg {

__host__ __device__ constexpr double fact(int n) {
    double r = 1.0; for (int i = 2; i <= n; i++) r *= (double)i; return r;
}

__host__ __device__ constexpr double csqrt(double x) {
    if (x <= 0.0) return 0.0;
    double g = (x > 1.0) ? x : 1.0;
    for (int i = 0; i < 100; i++) g = 0.5 * (g + x / g);
    return g;
}

__host__ __device__ constexpr double cgc(int j1, int m1, int j2, int m2, int J, int M) {
    if (m1 + m2 != M) return 0.0;
    int ad = j1 - j2; if (ad < 0) ad = -ad;
    if (J < ad || J > j1 + j2) return 0.0;
    double pref = (2.0 * J + 1.0) * fact(J + j1 - j2) * fact(J - j1 + j2) * fact(j1 + j2 - J)
                  / fact(j1 + j2 + J + 1);
    pref *= fact(J + M) * fact(J - M) * fact(j1 - m1) * fact(j1 + m1) * fact(j2 - m2) * fact(j2 + m2);
    double s = 0.0;
    for (int k = 0; k <= j1 + j2; k++) {
        int d0 = j1 + j2 - J - k, d1 = j1 - m1 - k, d2 = j2 + m2 - k;
        int d3 = J - j2 + m1 + k, d4 = J - j1 - m2 + k;
        if (d0 < 0 || d1 < 0 || d2 < 0 || d3 < 0 || d4 < 0) continue;
        double t = 1.0 / (fact(k) * fact(d0) * fact(d1) * fact(d2) * fact(d3) * fact(d4));
        s += (k & 1) ? -t : t;
    }
    return csqrt(pref) * s;
}

struct C2 { double re, im; };
struct URow { int n; int col[2]; C2 v[2]; };

__host__ __device__ constexpr URow urow(int l, int rr) {
    URow u{};
    const double R2 = 0.70710678118654752440;
    if (rr == l) { u.n = 1; u.col[0] = l; u.v[0].re = 1.0; u.v[0].im = 0.0; return u; }
    if (rr > l) {
        int m = rr - l; double sg = (m & 1) ? -1.0 : 1.0;
        u.n = 2;
        u.col[0] = l + m; u.v[0].re = sg * R2; u.v[0].im = 0.0;
        u.col[1] = l - m; u.v[1].re = R2;      u.v[1].im = 0.0;
        return u;
    }
    int m = l - rr; double sg = (m & 1) ? -1.0 : 1.0;
    u.n = 2;
    u.col[0] = l - m; u.v[0].re = 0.0; u.v[0].im = R2;
    u.col[1] = l + m; u.v[1].re = 0.0; u.v[1].im = -sg * R2;
    return u;
}

__host__ __device__ constexpr int dm(int i) { return (i == 0) ? 0 : ((i < 4) ? 1 : 2); }

__host__ __device__ constexpr float cg_entry(int A, int B, int C) {
    int l1 = dm(A), l2 = dm(B), l3 = dm(C);
    int a = A - l1 * l1, b = B - l2 * l2, c = C - l3 * l3;
    double gre = 0.0, gim = 0.0;
    int ad = l1 - l2; if (ad < 0) ad = -ad;
    if (l3 >= ad && l3 <= l1 + l2) {
        URow u1 = urow(l1, a), u2 = urow(l2, b), u3 = urow(l3, c);
        for (int i = 0; i < u1.n; i++)
            for (int j = 0; j < u2.n; j++)
                for (int k = 0; k < u3.n; k++) {
                    double cv = cgc(l1, u1.col[i] - l1, l2, u2.col[j] - l2,
                                    l3, u3.col[k] - l3);
                    if (cv == 0.0) continue;
                    double pre = u1.v[i].re * u2.v[j].re - u1.v[i].im * u2.v[j].im;
                    double pim = u1.v[i].re * u2.v[j].im + u1.v[i].im * u2.v[j].re;
                    double re = pre * u3.v[k].re + pim * u3.v[k].im;   // * conj(v3)
                    double im = pim * u3.v[k].re - pre * u3.v[k].im;
                    gre += re * cv; gim += im * cv;
                }
    }
    double agre = (gre < 0) ? -gre : gre;
    double agim = (gim < 0) ? -gim : gim;
    double R = (agim > agre) ? gim : gre;
    return (float)R;
}

// Is A[a][b] needed for ANY kept output c under maxdeg MD?
__host__ __device__ constexpr bool ab_used(int a, int b, int md) {
    for (int c = 0; c < 9; c++) {
        bool keep = (md == 2) || (c == 0);
        if (keep && cg_entry(a, b, c) != 0.0f) return true;
    }
    return false;
}
__host__ __device__ constexpr bool need_same(int a, int md) {
    for (int b = 0; b < 9; b++)
        if (!(b >= 1 && b <= 3) && ab_used(a, b, md)) return true;
    return false;
}
__host__ __device__ constexpr bool need_flip(int a, int md) {
    for (int b = 1; b <= 3; b++)
        if (ab_used(a, b, md)) return true;
    return false;
}

} // namespace cg

// ---------------------------------------------------------------------------
// Device scratch (static, no allocation)
// ---------------------------------------------------------------------------
__device__ float g_r[NEDGE];
__device__ float g_sh[NEDGE * 12];   // padded to 12 for float4 loads
__device__ float g_rad[NEDGE * 8];

__device__ float g_xbuf[2][NNODE * XS];   // ping-pong node state
__device__ float g_xEF[NNODE * XS];
__device__ float g_q[NNODE];
__device__ float g_aE[NNODE];
__device__ float g_dip[NNODE * 3];

__device__ __forceinline__ float warp_sum(float v) {
#pragma unroll
    for (int o = 16; o; o >>= 1) v += __shfl_xor_sync(0xffffffffu, v, o);
    return v;
}
__device__ __forceinline__ float sigm(float x) { return 1.0f / (1.0f + expf(-x)); }

// ---------------------------------------------------------------------------
// Compile-time CG contraction (message pass): y[c] += CG[a,b,c] * A[a*9+b]
// ---------------------------------------------------------------------------
template<int AB, int C, int MD>
__device__ __forceinline__ void cg_contract_c(const float (&A)[81], float (&y)[9]) {
    if constexpr (C < 9) {
        constexpr float v = cg::cg_entry(AB / 9, AB % 9, C);
        constexpr bool keep = (MD == 2) || (C == 0);
        if constexpr (v != 0.0f && keep) { y[C] += v * A[AB]; }
        cg_contract_c<AB, C + 1, MD>(A, y);
    }
}
template<int AB, int MD>
__device__ __forceinline__ void cg_contract_ab(const float (&A)[81], float (&y)[9]) {
    if constexpr (AB < 81) {
        cg_contract_c<AB, 0, MD>(A, y);
        cg_contract_ab<AB + 1, MD>(A, y);
    }
}

// Per-edge A accumulation, skipping entries that feed no kept output.
// (All guards strictly in if constexpr context — R10 lesson.)
template<int AB, int MD>
__device__ __forceinline__ void accum_ab(float (&A)[81], const float (&xsame)[9],
                                         const float (&xflip)[9], const float (&g)[9]) {
    if constexpr (AB < 81) {
        constexpr int a = AB / 9;
        constexpr int b = AB % 9;
        if constexpr (cg::ab_used(a, b, MD)) {
            float xa = (b >= 1 && b <= 3) ? xflip[a] : xsame[a];
            A[AB] += xa * g[b];
        }
        accum_ab<AB + 1, MD>(A, xsame, xflip, g);
    }
}

// Guarded x loads (compile-time pruned by MD).
template<int AA, int MD>
__device__ __forceinline__ void load_x(float (&xsame)[9], float (&xflip)[9],
                                       const float* __restrict__ xs,
                                       int sameoff, int flipoff, int lane) {
    if constexpr (AA < 9) {
        if constexpr (cg::need_same(AA, MD)) xsame[AA] = xs[sameoff + AA * NF + lane];
        else                                 xsame[AA] = 0.0f;
        if constexpr (cg::need_flip(AA, MD)) xflip[AA] = xs[flipoff + AA * NF + lane];
        else                                 xflip[AA] = 0.0f;
        load_x<AA + 1, MD>(xsame, xflip, xs, sameoff, flipoff, lane);
    }
}

// ---------------------------------------------------------------------------
// Single-output-parity couple: O[c] += CG*Wp*(U0[a]*VP[b] + U1[a]*VQ[b]).
// For out-parity 0: (VP,VQ)=(V0,V1); for out-parity 1: (VP,VQ)=(V1,V0).
// ---------------------------------------------------------------------------
template<int AB, int C, int MAXC>
__device__ __forceinline__ void couple1_c(const float (&U0)[9], const float (&U1)[9],
                                          const float (&VP)[9], const float (&VQ)[9],
                                          const float (&wt)[27], float (&O)[9]) {
    if constexpr (C < MAXC) {
        constexpr int a = AB / 9;
        constexpr int b = AB % 9;
        constexpr float v = cg::cg_entry(a, b, C);
        if constexpr (v != 0.0f) {
            constexpr int lidx = cg::dm(a) * 9 + cg::dm(b) * 3 + cg::dm(C);
            float wv = v * wt[lidx];
            O[C] += wv * (U0[a] * VP[b] + U1[a] * VQ[b]);
        }
        couple1_c<AB, C + 1, MAXC>(U0, U1, VP, VQ, wt, O);
    }
}
template<int AB, int MAXC>
__device__ __forceinline__ void couple1_ab(const float (&U0)[9], const float (&U1)[9],
                                           const float (&VP)[9], const float (&VQ)[9],
                                           const float (&wt)[27], float (&O)[9]) {
    if constexpr (AB < 81) {
        couple1_c<AB, 0, MAXC>(U0, U1, VP, VQ, wt, O);
        couple1_ab<AB + 1, MAXC>(U0, U1, VP, VQ, wt, O);
    }
}
template<int MAXC>
__device__ __forceinline__ void couple1(const float (&U0)[9], const float (&U1)[9],
                                        const float (&VP)[9], const float (&VQ)[9],
                                        const float (&wt)[27], float (&O)[9]) {
#pragma unroll
    for (int c = 0; c < 9; c++) O[c] = 0.0f;
    couple1_ab<0, MAXC>(U0, U1, VP, VQ, wt, O);
}

// ---------------------------------------------------------------------------
// Per-warp dense of 9 rows via smem staging + broadcast float4 LDS.
// scr = 288-float per-warp scratch.
// ---------------------------------------------------------------------------
__device__ __forceinline__ void dense1(float (&X)[9], const float* __restrict__ W,
                                       int lane, float* scr) {
    float wc[32];
#pragma unroll
    for (int k = 0; k < 32; k++) wc[k] = W[k * NF + lane];
    __syncwarp();
#pragma unroll
    for (int m = 0; m < 9; m++) scr[m * NF + lane] = X[m];
    __syncwarp();
#pragma unroll
    for (int m = 0; m < 9; m++) {
        const float4* r = (const float4*)(scr + m * NF);
        float a = 0.0f;
#pragma unroll
        for (int kk = 0; kk < 8; kk++) {
            float4 v = r[kk];
            a += v.x * wc[kk * 4 + 0] + v.y * wc[kk * 4 + 1]
               + v.z * wc[kk * 4 + 2] + v.w * wc[kk * 4 + 3];
        }
        X[m] = a;
    }
    __syncwarp();
}

// ---------------------------------------------------------------------------
// Fused edge precompute + state init (128 blocks x 256)
// ---------------------------------------------------------------------------
__global__ void __launch_bounds__(256) edgeinit_kernel(
    const float* __restrict__ pos,
    const int* __restrict__ dst_idx, const int* __restrict__ src_idx,
    const int* __restrict__ Zarr, const float* __restrict__ embed,
    const float* __restrict__ Ef) {
    int e = blockIdx.x * 256 + threadIdx.x;
    if (e < NEDGE) {
        int mol = e / EPM, k = e % EPM;
        int d = dst_idx[k] + mol * NATOM;
        int s = src_idx[k] + mol * NATOM;
        float dx = pos[s * 3 + 0] - pos[d * 3 + 0];
        float dy = pos[s * 3 + 1] - pos[d * 3 + 1];
        float dz = pos[s * 3 + 2] - pos[d * 3 + 2];
        float r = sqrtf(dx * dx + dy * dy + dz * dz);
        g_r[e] = r;
        float inv = 1.0f / (r + 1e-10f);
        float x = dx * inv, y = dy * inv, z = dz * inv;
        const float s3 = 1.7320508075688772f;
        g_sh[e * 12 + 0] = 1.0f;
        g_sh[e * 12 + 1] = y;
        g_sh[e * 12 + 2] = z;
        g_sh[e * 12 + 3] = x;
        g_sh[e * 12 + 4] = s3 * x * y;
        g_sh[e * 12 + 5] = s3 * y * z;
        g_sh[e * 12 + 6] = 0.5f * (3.0f * z * z - 1.0f);
        g_sh[e * 12 + 7] = s3 * x * z;
        g_sh[e * 12 + 8] = 0.5f * s3 * (x * x - y * y);

        float fb = 1.0f / (1.0f + r);
        float omf = 1.0f - fb;
        float u2 = (r * 0.2f) * (r * 0.2f);
        float inner = fmaxf(1.0f - u2, 1e-6f);
        float cut = (r < 5.0f) ? expf(1.0f - 1.0f / inner) : 0.0f;
        const float binom[8] = {1.f, 7.f, 21.f, 35.f, 35.f, 21.f, 7.f, 1.f};
        float fp[8], op[8];
        fp[0] = 1.0f; op[0] = 1.0f;
#pragma unroll
        for (int i = 1; i < 8; i++) { fp[i] = fp[i - 1] * fb; op[i] = op[i - 1] * omf; }
#pragma unroll
        for (int i = 0; i < 8; i++)
            g_rad[e * 8 + i] = binom[i] * fp[i] * op[7 - i] * cut;
    }

    int node = blockIdx.x * 8 + (threadIdx.x >> 5);
    int lane = threadIdx.x & 31;
    int mol = node >> 5;
    int Z = Zarr[node];
    float* xo = g_xbuf[0] + node * XS;
    float* xe = g_xEF + node * XS;
    float e0 = Ef[mol * 3 + 0], e1 = Ef[mol * 3 + 1], e2 = Ef[mol * 3 + 2];
#pragma unroll
    for (int p = 0; p < 2; p++)
#pragma unroll
        for (int m = 0; m < 9; m++) {
            float xv = (p == 0 && m == 0) ? embed[Z * NF + lane] : 0.0f;
            float ev = (m == 1) ? e0 : ((m == 2) ? e1 : ((m == 3) ? e2 : 0.0f));
            xo[(p * 9 + m) * NF + lane] = xv;
            xe[(p * 9 + m) * NF + lane] = ev;
        }
}

// ---------------------------------------------------------------------------
// Kernel parameter bundle
// ---------------------------------------------------------------------------
struct KParams {
    const float* Wmp; const float* Wd; const float* bd;
    const float* Wt; const float* Wtd1; const float* Wtd2; const float* Wtdp;
    const float* Wh; const float* bh; const float* Wq;
    const float* Wdip1; const float* Wdip2; const float* Wdipp; const float* wdip;
    const float* We; const float* be; const float* ebias;
    const int* Zarr;
};

// ---------------------------------------------------------------------------
// Fused message pass + node update (+ optional readout). One block per node,
// 64 threads; warp w owns parity w through msg AND update.
// __launch_bounds__(64, 7): guarantee >=7 blocks/SM (one wave for the
// 1024-block grid; reg cap 146).
// ---------------------------------------------------------------------------
template<int MD, bool RO>
__global__ void __launch_bounds__(64, 7) msgupd_kernel(int inbuf, int iter, KParams kp) {
    __shared__ float sStage[4][9 * NF];   // cross-parity staging (X0,X1,E0,E1)/(U0,U1,V0,V1)
    __shared__ float sScr[2][9 * NF];     // per-warp dense scratch
    __shared__ float sG[NF];              // gate broadcast

    int node = blockIdx.x;
    int w = threadIdx.x >> 5;
    int lane = threadIdx.x & 31;
    int mol = node >> 5, datom = node & 31;
    const float* xin = g_xbuf[inbuf];
    float* scr = sScr[w];

    // ================= message (warp w -> out-parity w) =================
    float wmp0[8], wmp1[8], wmp2[8];
#pragma unroll
    for (int nb = 0; nb < 8; nb++) {
        wmp0[nb] = kp.Wmp[((iter * 3 + 0) * 8 + nb) * NF + lane];
        wmp1[nb] = kp.Wmp[((iter * 3 + 1) * 8 + nb) * NF + lane];
        wmp2[nb] = kp.Wmp[((iter * 3 + 2) * 8 + nb) * NF + lane];
    }

    float A[81];
#pragma unroll
    for (int i = 0; i < 81; i++) A[i] = 0.0f;

    int ebase = mol * EPM + datom * 31;
    int sameoff = w * 288;
    int flipoff = 288 - sameoff;
    const float* xmol = xin + mol * NATOM * XS;

    // unroll 8: batch independent per-edge load groups across iterations to
    // raise MLP (R14 proved unroll4 cut the kernel ~30%; this loop is
    // load-latency-bound).
#pragma unroll 8
    for (int t = 0; t < 31; t++) {
        int e = ebase + t;
        int satom = t + (t >= datom ? 1 : 0);
        const float* xs = xmol + satom * XS;

        float4 ra = *(const float4*)(g_rad + e * 8);
        float4 rb = *(const float4*)(g_rad + e * 8 + 4);
        float R0 = ra.x * wmp0[0] + ra.y * wmp0[1] + ra.z * wmp0[2] + ra.w * wmp0[3]
                 + rb.x * wmp0[4] + rb.y * wmp0[5] + rb.z * wmp0[6] + rb.w * wmp0[7];
        float R1 = ra.x * wmp1[0] + ra.y * wmp1[1] + ra.z * wmp1[2] + ra.w * wmp1[3]
                 + rb.x * wmp1[4] + rb.y * wmp1[5] + rb.z * wmp1[6] + rb.w * wmp1[7];
        float R2v = ra.x * wmp2[0] + ra.y * wmp2[1] + ra.z * wmp2[2] + ra.w * wmp2[3]
                  + rb.x * wmp2[4] + rb.y * wmp2[5] + rb.z * wmp2[6] + rb.w * wmp2[7];

        float4 s0 = *(const float4*)(g_sh + e * 12);
        float4 s1 = *(const float4*)(g_sh + e * 12 + 4);
        float  s8 = g_sh[e * 12 + 8];
        float g[9];
        g[0] = s0.x * R0;
        g[1] = s0.y * R1; g[2] = s0.z * R1; g[3] = s0.w * R1;
        g[4] = s1.x * R2v; g[5] = s1.y * R2v; g[6] = s1.z * R2v;
        g[7] = s1.w * R2v; g[8] = s8 * R2v;

        float xsame[9], xflip[9];
        load_x<0, MD>(xsame, xflip, xs, sameoff, flipoff, lane);
        accum_ab<0, MD>(A, xsame, xflip, g);
    }

    float Y[9];
#pragma unroll
    for (int c = 0; c < 9; c++) Y[c] = 0.0f;
    cg_contract_ab<0, MD>(A, Y);   // Y = msg for parity w

    // ================= update (parity-split across warps) =================
    float X[9];
    const float* xg = xin + node * XS + w * 288;
#pragma unroll
    for (int m = 0; m < 9; m++) X[m] = xg[m * NF + lane] + Y[m];

    // silu gate 1 (gate = sigm of parity0 m0)
    if (w == 0) sG[lane] = X[0];
    __syncthreads();
    float gate = sigm(sG[lane]);
#pragma unroll
    for (int m = 0; m < 9; m++) X[m] *= gate;

    // dense Wd (own parity) + bias + silu gate 2
    dense1(X, kp.Wd + iter * NF * NF, lane, scr);
    if (w == 0) X[0] += kp.bd[iter * NF + lane];
    __syncthreads();
    if (w == 0) sG[lane] = X[0];
    __syncthreads();
    gate = sigm(sG[lane]);
#pragma unroll
    for (int m = 0; m < 9; m++) X[m] *= gate;

    // couple(x, xEF, Wt): stage X and E, compute own out-parity
    float E[9];
    float* xeg = g_xEF + node * XS + w * 288;
#pragma unroll
    for (int m = 0; m < 9; m++) {
        E[m] = xeg[m * NF + lane];
        sStage[w][m * NF + lane] = X[m];       // X0 / X1
        sStage[2 + w][m * NF + lane] = E[m];   // E0 / E1
    }
    __syncthreads();
    float wt[27];
#pragma unroll
    for (int j = 0; j < 27; j++) wt[j] = kp.Wt[(iter * 27 + j) * NF + lane];
    {
        float XA0[9], XA1[9], EP[9], EQ[9];
#pragma unroll
        for (int m = 0; m < 9; m++) {
            XA0[m] = sStage[0][m * NF + lane];
            XA1[m] = sStage[1][m * NF + lane];
            EP[m]  = sStage[2 + w][m * NF + lane];
            EQ[m]  = sStage[3 - w][m * NF + lane];
        }
        float O[9];
        couple1<9>(XA0, XA1, EP, EQ, wt, O);
#pragma unroll
        for (int m = 0; m < 9; m++) {
            xeg[m * NF + lane] = O[m];
            X[m] += O[m];
        }
    }

    // tensor_dense: U = X@Wtd1, V = X@Wtd2 (own parity), couple
    float U[9], V[9];
#pragma unroll
    for (int m = 0; m < 9; m++) { U[m] = X[m]; V[m] = X[m]; }
    dense1(U, kp.Wtd1 + iter * NF * NF, lane, scr);
    dense1(V, kp.Wtd2 + iter * NF * NF, lane, scr);
    __syncthreads();   // previous stage fully consumed
#pragma unroll
    for (int m = 0; m < 9; m++) {
        sStage[w][m * NF + lane] = U[m];       // U0 / U1
        sStage[2 + w][m * NF + lane] = V[m];   // V0 / V1
    }
    __syncthreads();
#pragma unroll
    for (int j = 0; j < 27; j++) wt[j] = kp.Wtdp[(iter * 27 + j) * NF + lane];
    {
        float U0[9], U1[9], VP[9], VQ[9];
#pragma unroll
        for (int m = 0; m < 9; m++) {
            U0[m] = sStage[0][m * NF + lane];
            U1[m] = sStage[1][m * NF + lane];
            VP[m] = sStage[2 + w][m * NF + lane];
            VQ[m] = sStage[3 - w][m * NF + lane];
        }
        float O[9];
        couple1<9>(U0, U1, VP, VQ, wt, O);
#pragma unroll
        for (int m = 0; m < 9; m++) X[m] = O[m] + Y[m];   // final x of this iter
    }

    if constexpr (!RO) {
        float* xo = g_xbuf[inbuf ^ 1] + node * XS + w * 288;
#pragma unroll
        for (int m = 0; m < 9; m++) xo[m * NF + lane] = X[m];
        return;
    } else {
        // ================= readout (fused, parity-split) =================
#pragma unroll
        for (int i = 0; i < 4; i++) {
            dense1(X, kp.Wh + i * NF * NF, lane, scr);
            if (w == 0) X[0] += kp.bh[i * NF + lane];
            __syncthreads();
            if (w == 0) sG[lane] = X[0];
            __syncthreads();
            float g2 = sigm(sG[lane]);
#pragma unroll
            for (int m = 0; m < 9; m++) X[m] *= g2;
        }
        dense1(X, kp.Wh + 4 * NF * NF, lane, scr);
        if (w == 0) X[0] += kp.bh[4 * NF + lane];

        // dipole path: xd keeps [0,0] (parity0) and [1,1:4] (parity1)
        float Ud[9], Vd[9];
#pragma unroll
        for (int m = 0; m < 9; m++) Ud[m] = 0.0f;
        if (w == 0) { Ud[0] = X[0]; }
        else       { Ud[1] = X[1]; Ud[2] = X[2]; Ud[3] = X[3]; }
#pragma unroll
        for (int m = 0; m < 9; m++) Vd[m] = Ud[m];
        dense1(Ud, kp.Wdip1, lane, scr);
        dense1(Vd, kp.Wdip2, lane, scr);
        __syncthreads();
#pragma unroll
        for (int m = 0; m < 9; m++) {
            sStage[w][m * NF + lane] = Ud[m];
            sStage[2 + w][m * NF + lane] = Vd[m];
        }
        __syncthreads();

        if (w == 0) {
            // charges + site energy from scal = X[0] (parity0 m0)
            float scal = X[0];
            float q = warp_sum(scal * kp.Wq[lane]);
            float ae = warp_sum(scal * kp.We[lane]);
            if (lane == 0) {
                g_q[node] = q;
                g_aE[node] = ae + kp.be[0] + kp.ebias[kp.Zarr[node]];
            }
        } else {
            // dipole: O1[c] for c=1..3
            float wtd[27];
#pragma unroll
            for (int j = 0; j < 27; j++) wtd[j] = kp.Wdipp[j * NF + lane];
            float U0[9], U1[9], VP[9], VQ[9];
#pragma unroll
            for (int m = 0; m < 9; m++) {
                U0[m] = sStage[0][m * NF + lane];
                U1[m] = sStage[1][m * NF + lane];
                VP[m] = sStage[3][m * NF + lane];   // out-parity 1: VP=V1
                VQ[m] = sStage[2][m * NF + lane];   // VQ=V0
            }
            float O[9];
            couple1<4>(U0, U1, VP, VQ, wtd, O);
            float wd = kp.wdip[lane];
            float d0 = warp_sum(O[1] * wd);
            float d1 = warp_sum(O[2] * wd);
            float d2 = warp_sum(O[3] * wd);
            if (lane == 0) {
                g_dip[node * 3 + 0] = d0;
                g_dip[node * 3 + 1] = d1;
                g_dip[node * 3 + 2] = d2;
            }
        }
    }
}

// ---------------------------------------------------------------------------
// Per-molecule reduction: energy (+Coulomb), dipole
// ---------------------------------------------------------------------------
__global__ void __launch_bounds__(32) reduce_kernel(
    const float* __restrict__ pos,
    const int* __restrict__ dst_idx, const int* __restrict__ src_idx,
    float* __restrict__ out) {
    int mol = blockIdx.x;
    int lane = threadIdx.x;
    int node = mol * NATOM + lane;

    float px = pos[node * 3 + 0], py = pos[node * 3 + 1], pz = pos[node * 3 + 2];
    float cx = warp_sum(px) * (1.0f / 32.0f);
    float cy = warp_sum(py) * (1.0f / 32.0f);
    float cz = warp_sum(pz) * (1.0f / 32.0f);

    float e = warp_sum(g_aE[node]);
    float q = g_q[node];
    float dx = warp_sum(q * (px - cx) + g_dip[node * 3 + 0]);
    float dy = warp_sum(q * (py - cy) + g_dip[node * 3 + 1]);
    float dz = warp_sum(q * (pz - cz) + g_dip[node * 3 + 2]);

    float cacc = 0.0f;
    for (int t = 0; t < 31; t++) {
        int k = t * 32 + lane;
        int e_idx = mol * EPM + k;
        int s = src_idx[k] + mol * NATOM;
        int d = dst_idx[k] + mol * NATOM;
        cacc += g_q[s] * g_q[d] / (g_r[e_idx] + 1e-10f);
    }
    float coul = warp_sum(cacc) * 0.5f;

    if (lane == 0) {
        out[mol] = e + coul * 14.399645f;
        out[NMOL + mol * 3 + 0] = dx;
        out[NMOL + mol * 3 + 1] = dy;
        out[NMOL + mol * 3 + 2] = dz;
    }
}

// ---------------------------------------------------------------------------
// Launch
// ---------------------------------------------------------------------------
extern "C" void kernel_launch(void* const* d_in, const int* in_sizes, int n_in,
                              void* d_out, int out_size) {
    int sft = (n_in >= 24) ? 1 : 0;

    const int*   Zarr   = (const int*)  d_in[0];
    const float* pos    = (const float*)d_in[1];
    const float* Ef     = (const float*)d_in[2];
    const int*   dsti   = (const int*)  d_in[3];
    const int*   srci   = (const int*)  d_in[4];

    KParams kp;
    kp.Wmp    = (const float*)d_in[6 + sft];
    kp.Wd     = (const float*)d_in[7 + sft];
    kp.bd     = (const float*)d_in[8 + sft];
    kp.Wt     = (const float*)d_in[9 + sft];
    kp.Wtd1   = (const float*)d_in[10 + sft];
    kp.Wtd2   = (const float*)d_in[11 + sft];
    kp.Wtdp   = (const float*)d_in[12 + sft];
    kp.Wh     = (const float*)d_in[13 + sft];
    kp.bh     = (const float*)d_in[14 + sft];
    kp.Wq     = (const float*)d_in[15 + sft];
    kp.Wdip1  = (const float*)d_in[16 + sft];
    kp.Wdip2  = (const float*)d_in[17 + sft];
    kp.Wdipp  = (const float*)d_in[18 + sft];
    kp.wdip   = (const float*)d_in[19 + sft];
    kp.We     = (const float*)d_in[20 + sft];
    kp.be     = (const float*)d_in[21 + sft];
    kp.ebias  = (const float*)d_in[22 + sft];
    kp.Zarr   = Zarr;

    const float* embed = (const float*)d_in[5 + sft];
    float* out = (float*)d_out;

    edgeinit_kernel<<<128, 256>>>(pos, dsti, srci, Zarr, embed, Ef);

    msgupd_kernel<2, false><<<NNODE, 64>>>(0, 0, kp);
    msgupd_kernel<2, false><<<NNODE, 64>>>(1, 1, kp);
    msgupd_kernel<0, true><<<NNODE, 64>>>(0, 2, kp);

    reduce_kernel<<<NMOL, 32>>>(pos, dsti, srci, out);
    (void)in_sizes; (void)out_size;
}

// round 16
// speedup vs baseline: 1.1842x; 1.1842x over previous
#include <cuda_runtime.h>
#include <math.h>

// ---------------------------------------------------------------------------
// Constants fixed by setup_inputs
// ---------------------------------------------------------------------------
#define NF      32
#define XS      576        // 2*9*32 floats per node
#define NNODE   1024
#define NMOL    32
#define NATOM   32
#define EPM     992
#define NEDGE   31744

// ---------------------------------------------------------------------------
// Compile-time Clebsch-Gordan per-entry evaluation (replicates _build_cg).
// ---------------------------------------------------------------------------
namespace cg {

__host__ __device__ constexpr double fact(int n) {
    double r = 1.0; for (int i = 2; i <= n; i++) r *= (double)i; return r;
}

__host__ __device__ constexpr double csqrt(double x) {
    if (x <= 0.0) return 0.0;
    double g = (x > 1.0) ? x : 1.0;
    for (int i = 0; i < 100; i++) g = 0.5 * (g + x / g);
    return g;
}

__host__ __device__ constexpr double cgc(int j1, int m1, int j2, int m2, int J, int M) {
    if (m1 + m2 != M) return 0.0;
    int ad = j1 - j2; if (ad < 0) ad = -ad;
    if (J < ad || J > j1 + j2) return 0.0;
    double pref = (2.0 * J + 1.0) * fact(J + j1 - j2) * fact(J - j1 + j2) * fact(j1 + j2 - J)
                  / fact(j1 + j2 + J + 1);
    pref *= fact(J + M) * fact(J - M) * fact(j1 - m1) * fact(j1 + m1) * fact(j2 - m2) * fact(j2 + m2);
    double s = 0.0;
    for (int k = 0; k <= j1 + j2; k++) {
        int d0 = j1 + j2 - J - k, d1 = j1 - m1 - k, d2 = j2 + m2 - k;
        int d3 = J - j2 + m1 + k, d4 = J - j1 - m2 + k;
        if (d0 < 0 || d1 < 0 || d2 < 0 || d3 < 0 || d4 < 0) continue;
        double t = 1.0 / (fact(k) * fact(d0) * fact(d1) * fact(d2) * fact(d3) * fact(d4));
        s += (k & 1) ? -t : t;
    }
    return csqrt(pref) * s;
}

struct C2 { double re, im; };
struct URow { int n; int col[2]; C2 v[2]; };

__host__ __device__ constexpr URow urow(int l, int rr) {
    URow u{};
    const double R2 = 0.70710678118654752440;
    if (rr == l) { u.n = 1; u.col[0] = l; u.v[0].re = 1.0; u.v[0].im = 0.0; return u; }
    if (rr > l) {
        int m = rr - l; double sg = (m & 1) ? -1.0 : 1.0;
        u.n = 2;
        u.col[0] = l + m; u.v[0].re = sg * R2; u.v[0].im = 0.0;
        u.col[1] = l - m; u.v[1].re = R2;      u.v[1].im = 0.0;
        return u;
    }
    int m = l - rr; double sg = (m & 1) ? -1.0 : 1.0;
    u.n = 2;
    u.col[0] = l - m; u.v[0].re = 0.0; u.v[0].im = R2;
    u.col[1] = l + m; u.v[1].re = 0.0; u.v[1].im = -sg * R2;
    return u;
}

__host__ __device__ constexpr int dm(int i) { return (i == 0) ? 0 : ((i < 4) ? 1 : 2); }

__host__ __device__ constexpr float cg_entry(int A, int B, int C) {
    int l1 = dm(A), l2 = dm(B), l3 = dm(C);
    int a = A - l1 * l1, b = B - l2 * l2, c = C - l3 * l3;
    double gre = 0.0, gim = 0.0;
    int ad = l1 - l2; if (ad < 0) ad = -ad;
    if (l3 >= ad && l3 <= l1 + l2) {
        URow u1 = urow(l1, a), u2 = urow(l2, b), u3 = urow(l3, c);
        for (int i = 0; i < u1.n; i++)
            for (int j = 0; j < u2.n; j++)
                for (int k = 0; k < u3.n; k++) {
                    double cv = cgc(l1, u1.col[i] - l1, l2, u2.col[j] - l2,
                                    l3, u3.col[k] - l3);
                    if (cv == 0.0) continue;
                    double pre = u1.v[i].re * u2.v[j].re - u1.v[i].im * u2.v[j].im;
                    double pim = u1.v[i].re * u2.v[j].im + u1.v[i].im * u2.v[j].re;
                    double re = pre * u3.v[k].re + pim * u3.v[k].im;   // * conj(v3)
                    double im = pim * u3.v[k].re - pre * u3.v[k].im;
                    gre += re * cv; gim += im * cv;
                }
    }
    double agre = (gre < 0) ? -gre : gre;
    double agim = (gim < 0) ? -gim : gim;
    double R = (agim > agre) ? gim : gre;
    return (float)R;
}

} // namespace cg

// ---------------------------------------------------------------------------
// Device scratch (static, no allocation)
// ---------------------------------------------------------------------------
__device__ float g_r[NEDGE];
__device__ float g_sh[NEDGE * 12];   // padded to 12 for float4 loads
__device__ float g_rad[NEDGE * 8];

__device__ float g_xbuf[2][NNODE * XS];   // ping-pong node state
__device__ float g_xEF[NNODE * XS];
__device__ float g_q[NNODE];
__device__ float g_aE[NNODE];
__device__ float g_dip[NNODE * 3];

__device__ __forceinline__ float warp_sum(float v) {
#pragma unroll
    for (int o = 16; o; o >>= 1) v += __shfl_xor_sync(0xffffffffu, v, o);
    return v;
}
__device__ __forceinline__ float sigm(float x) { return 1.0f / (1.0f + expf(-x)); }

// ---------------------------------------------------------------------------
// Compile-time CG contraction (message pass): y[c] += CG[a,b,c] * A[a*9+b]
// ---------------------------------------------------------------------------
template<int AB, int C, int MD>
__device__ __forceinline__ void cg_contract_c(const float (&A)[81], float (&y)[9]) {
    if constexpr (C < 9) {
        constexpr float v = cg::cg_entry(AB / 9, AB % 9, C);
        constexpr bool keep = (MD == 2) || (C == 0);
        if constexpr (v != 0.0f && keep) { y[C] += v * A[AB]; }
        cg_contract_c<AB, C + 1, MD>(A, y);
    }
}
template<int AB, int MD>
__device__ __forceinline__ void cg_contract_ab(const float (&A)[81], float (&y)[9]) {
    if constexpr (AB < 81) {
        cg_contract_c<AB, 0, MD>(A, y);
        cg_contract_ab<AB + 1, MD>(A, y);
    }
}

// ---------------------------------------------------------------------------
// Single-output-parity couple: O[c] += CG*Wp*(U0[a]*VP[b] + U1[a]*VQ[b]).
// For out-parity 0: (VP,VQ)=(V0,V1); for out-parity 1: (VP,VQ)=(V1,V0).
// ---------------------------------------------------------------------------
template<int AB, int C, int MAXC>
__device__ __forceinline__ void couple1_c(const float (&U0)[9], const float (&U1)[9],
                                          const float (&VP)[9], const float (&VQ)[9],
                                          const float (&wt)[27], float (&O)[9]) {
    if constexpr (C < MAXC) {
        constexpr int a = AB / 9;
        constexpr int b = AB % 9;
        constexpr float v = cg::cg_entry(a, b, C);
        if constexpr (v != 0.0f) {
            constexpr int lidx = cg::dm(a) * 9 + cg::dm(b) * 3 + cg::dm(C);
            float wv = v * wt[lidx];
            O[C] += wv * (U0[a] * VP[b] + U1[a] * VQ[b]);
        }
        couple1_c<AB, C + 1, MAXC>(U0, U1, VP, VQ, wt, O);
    }
}
template<int AB, int MAXC>
__device__ __forceinline__ void couple1_ab(const float (&U0)[9], const float (&U1)[9],
                                           const float (&VP)[9], const float (&VQ)[9],
                                           const float (&wt)[27], float (&O)[9]) {
    if constexpr (AB < 81) {
        couple1_c<AB, 0, MAXC>(U0, U1, VP, VQ, wt, O);
        couple1_ab<AB + 1, MAXC>(U0, U1, VP, VQ, wt, O);
    }
}
template<int MAXC>
__device__ __forceinline__ void couple1(const float (&U0)[9], const float (&U1)[9],
                                        const float (&VP)[9], const float (&VQ)[9],
                                        const float (&wt)[27], float (&O)[9]) {
#pragma unroll
    for (int c = 0; c < 9; c++) O[c] = 0.0f;
    couple1_ab<0, MAXC>(U0, U1, VP, VQ, wt, O);
}

// Sparse dipole couple term for out-parity 1, output component C (1..3):
// xd has U0 nonzero only at a=0, U1 only at a=1..3 (same for V).
// O1[C] = CG(0,C,C)*Wp[0,1,1]*U0[0]*V1[C] + CG(C,0,C)*Wp[1,0,1]*U1[C]*V0[0]
template<int C>
__device__ __forceinline__ float dip_term(float U00, float V00,
                                          const float (&Ur)[3], const float (&Vr)[3],
                                          const float* __restrict__ Wdipp, int lane) {
    constexpr float cg1 = cg::cg_entry(0, C, C);
    constexpr float cg2 = cg::cg_entry(C, 0, C);
    constexpr int lidx1 = cg::dm(0) * 9 + cg::dm(C) * 3 + cg::dm(C);
    constexpr int lidx2 = cg::dm(C) * 9 + cg::dm(0) * 3 + cg::dm(C);
    float acc = 0.0f;
    if constexpr (cg1 != 0.0f) acc += cg1 * Wdipp[lidx1 * NF + lane] * (U00 * Vr[C - 1]);
    if constexpr (cg2 != 0.0f) acc += cg2 * Wdipp[lidx2 * NF + lane] * (Ur[C - 1] * V00);
    return acc;
}

// ---------------------------------------------------------------------------
// Per-warp dense of 9 rows via smem staging + broadcast float4 LDS.
// scr = 288-float per-warp scratch.
// ---------------------------------------------------------------------------
__device__ __forceinline__ void dense1(float (&X)[9], const float* __restrict__ W,
                                       int lane, float* scr) {
    float wc[32];
#pragma unroll
    for (int k = 0; k < 32; k++) wc[k] = W[k * NF + lane];
    __syncwarp();
#pragma unroll
    for (int m = 0; m < 9; m++) scr[m * NF + lane] = X[m];
    __syncwarp();
#pragma unroll
    for (int m = 0; m < 9; m++) {
        const float4* r = (const float4*)(scr + m * NF);
        float a = 0.0f;
#pragma unroll
        for (int kk = 0; kk < 8; kk++) {
            float4 v = r[kk];
            a += v.x * wc[kk * 4 + 0] + v.y * wc[kk * 4 + 1]
               + v.z * wc[kk * 4 + 2] + v.w * wc[kk * 4 + 3];
        }
        X[m] = a;
    }
    __syncwarp();
}

// 3-row variant for the slimmed readout.
__device__ __forceinline__ void dense3(float (&X)[3], const float* __restrict__ W,
                                       int lane, float* scr) {
    float wc[32];
#pragma unroll
    for (int k = 0; k < 32; k++) wc[k] = W[k * NF + lane];
    __syncwarp();
#pragma unroll
    for (int m = 0; m < 3; m++) scr[m * NF + lane] = X[m];
    __syncwarp();
#pragma unroll
    for (int m = 0; m < 3; m++) {
        const float4* r = (const float4*)(scr + m * NF);
        float a = 0.0f;
#pragma unroll
        for (int kk = 0; kk < 8; kk++) {
            float4 v = r[kk];
            a += v.x * wc[kk * 4 + 0] + v.y * wc[kk * 4 + 1]
               + v.z * wc[kk * 4 + 2] + v.w * wc[kk * 4 + 3];
        }
        X[m] = a;
    }
    __syncwarp();
}

// ---------------------------------------------------------------------------
// Fused edge precompute + state init (128 blocks x 256)
// ---------------------------------------------------------------------------
__global__ void __launch_bounds__(256) edgeinit_kernel(
    const float* __restrict__ pos,
    const int* __restrict__ dst_idx, const int* __restrict__ src_idx,
    const int* __restrict__ Zarr, const float* __restrict__ embed,
    const float* __restrict__ Ef) {
    int e = blockIdx.x * 256 + threadIdx.x;
    if (e < NEDGE) {
        int mol = e / EPM, k = e % EPM;
        int d = dst_idx[k] + mol * NATOM;
        int s = src_idx[k] + mol * NATOM;
        float dx = pos[s * 3 + 0] - pos[d * 3 + 0];
        float dy = pos[s * 3 + 1] - pos[d * 3 + 1];
        float dz = pos[s * 3 + 2] - pos[d * 3 + 2];
        float r = sqrtf(dx * dx + dy * dy + dz * dz);
        g_r[e] = r;
        float inv = 1.0f / (r + 1e-10f);
        float x = dx * inv, y = dy * inv, z = dz * inv;
        const float s3 = 1.7320508075688772f;
        g_sh[e * 12 + 0] = 1.0f;
        g_sh[e * 12 + 1] = y;
        g_sh[e * 12 + 2] = z;
        g_sh[e * 12 + 3] = x;
        g_sh[e * 12 + 4] = s3 * x * y;
        g_sh[e * 12 + 5] = s3 * y * z;
        g_sh[e * 12 + 6] = 0.5f * (3.0f * z * z - 1.0f);
        g_sh[e * 12 + 7] = s3 * x * z;
        g_sh[e * 12 + 8] = 0.5f * s3 * (x * x - y * y);

        float fb = 1.0f / (1.0f + r);
        float omf = 1.0f - fb;
        float u2 = (r * 0.2f) * (r * 0.2f);
        float inner = fmaxf(1.0f - u2, 1e-6f);
        float cut = (r < 5.0f) ? expf(1.0f - 1.0f / inner) : 0.0f;
        const float binom[8] = {1.f, 7.f, 21.f, 35.f, 35.f, 21.f, 7.f, 1.f};
        float fp[8], op[8];
        fp[0] = 1.0f; op[0] = 1.0f;
#pragma unroll
        for (int i = 1; i < 8; i++) { fp[i] = fp[i - 1] * fb; op[i] = op[i - 1] * omf; }
#pragma unroll
        for (int i = 0; i < 8; i++)
            g_rad[e * 8 + i] = binom[i] * fp[i] * op[7 - i] * cut;
    }

    int node = blockIdx.x * 8 + (threadIdx.x >> 5);
    int lane = threadIdx.x & 31;
    int mol = node >> 5;
    int Z = Zarr[node];
    float* xo = g_xbuf[0] + node * XS;
    float* xe = g_xEF + node * XS;
    float e0 = Ef[mol * 3 + 0], e1 = Ef[mol * 3 + 1], e2 = Ef[mol * 3 + 2];
#pragma unroll
    for (int p = 0; p < 2; p++)
#pragma unroll
        for (int m = 0; m < 9; m++) {
            float xv = (p == 0 && m == 0) ? embed[Z * NF + lane] : 0.0f;
            float ev = (m == 1) ? e0 : ((m == 2) ? e1 : ((m == 3) ? e2 : 0.0f));
            xo[(p * 9 + m) * NF + lane] = xv;
            xe[(p * 9 + m) * NF + lane] = ev;
        }
}

// ---------------------------------------------------------------------------
// Kernel parameter bundle
// ---------------------------------------------------------------------------
struct KParams {
    const float* Wmp; const float* Wd; const float* bd;
    const float* Wt; const float* Wtd1; const float* Wtd2; const float* Wtdp;
    const float* Wh; const float* bh; const float* Wq;
    const float* Wdip1; const float* Wdip2; const float* Wdipp; const float* wdip;
    const float* We; const float* be; const float* ebias;
    const int* Zarr;
};

// ---------------------------------------------------------------------------
// Fused message pass + node update (+ optional readout). One block per node,
// 64 threads; warp w owns parity w through msg AND update.
// __launch_bounds__(64, 7): one wave for the 1024-block grid (reg cap 146).
// ---------------------------------------------------------------------------
template<int MD, bool RO>
__global__ void __launch_bounds__(64, 7) msgupd_kernel(int inbuf, int iter, KParams kp) {
    __shared__ float sStage[4][9 * NF];   // cross-parity staging (X0,X1,E0,E1)/(U0,U1,V0,V1)
    __shared__ float sScr[2][9 * NF];     // per-warp dense scratch
    __shared__ float sG[NF];              // gate broadcast

    int node = blockIdx.x;
    int w = threadIdx.x >> 5;
    int lane = threadIdx.x & 31;
    int mol = node >> 5, datom = node & 31;
    const float* xin = g_xbuf[inbuf];
    float* scr = sScr[w];

    // ================= message (warp w -> out-parity w) =================
    float wmp0[8], wmp1[8], wmp2[8];
#pragma unroll
    for (int nb = 0; nb < 8; nb++) {
        wmp0[nb] = kp.Wmp[((iter * 3 + 0) * 8 + nb) * NF + lane];
        wmp1[nb] = kp.Wmp[((iter * 3 + 1) * 8 + nb) * NF + lane];
        wmp2[nb] = kp.Wmp[((iter * 3 + 2) * 8 + nb) * NF + lane];
    }

    float A[81];
#pragma unroll
    for (int i = 0; i < 81; i++) A[i] = 0.0f;

    int ebase = mol * EPM + datom * 31;
    int sameoff = w * 288;
    int flipoff = 288 - sameoff;
    const float* xmol = xin + mol * NATOM * XS;

    // unroll 4: validated R14 sweet spot (unroll8 regressed in R15).
#pragma unroll 4
    for (int t = 0; t < 31; t++) {
        int e = ebase + t;
        int satom = t + (t >= datom ? 1 : 0);
        const float* xs = xmol + satom * XS;

        float4 ra = *(const float4*)(g_rad + e * 8);
        float4 rb = *(const float4*)(g_rad + e * 8 + 4);
        float R0 = ra.x * wmp0[0] + ra.y * wmp0[1] + ra.z * wmp0[2] + ra.w * wmp0[3]
                 + rb.x * wmp0[4] + rb.y * wmp0[5] + rb.z * wmp0[6] + rb.w * wmp0[7];
        float R1 = ra.x * wmp1[0] + ra.y * wmp1[1] + ra.z * wmp1[2] + ra.w * wmp1[3]
                 + rb.x * wmp1[4] + rb.y * wmp1[5] + rb.z * wmp1[6] + rb.w * wmp1[7];
        float R2v = ra.x * wmp2[0] + ra.y * wmp2[1] + ra.z * wmp2[2] + ra.w * wmp2[3]
                  + rb.x * wmp2[4] + rb.y * wmp2[5] + rb.z * wmp2[6] + rb.w * wmp2[7];

        float4 s0 = *(const float4*)(g_sh + e * 12);
        float4 s1 = *(const float4*)(g_sh + e * 12 + 4);
        float  s8 = g_sh[e * 12 + 8];
        float g[9];
        g[0] = s0.x * R0;
        g[1] = s0.y * R1; g[2] = s0.z * R1; g[3] = s0.w * R1;
        g[4] = s1.x * R2v; g[5] = s1.y * R2v; g[6] = s1.z * R2v;
        g[7] = s1.w * R2v; g[8] = s8 * R2v;

        float xsame[9], xflip[9];
#pragma unroll
        for (int a = 0; a < 9; a++) {
            xsame[a] = xs[sameoff + a * NF + lane];
            xflip[a] = xs[flipoff + a * NF + lane];
        }
#pragma unroll
        for (int a = 0; a < 9; a++)
#pragma unroll
            for (int b = 0; b < 9; b++) {
                float xa = (b >= 1 && b <= 3) ? xflip[a] : xsame[a];
                A[a * 9 + b] += xa * g[b];
            }
    }

    float Y[9];
#pragma unroll
    for (int c = 0; c < 9; c++) Y[c] = 0.0f;
    cg_contract_ab<0, MD>(A, Y);   // Y = msg for parity w

    // ================= update (parity-split across warps) =================
    float X[9];
    const float* xg = xin + node * XS + w * 288;
#pragma unroll
    for (int m = 0; m < 9; m++) X[m] = xg[m * NF + lane] + Y[m];

    // silu gate 1 (gate = sigm of parity0 m0)
    if (w == 0) sG[lane] = X[0];
    __syncthreads();
    float gate = sigm(sG[lane]);
#pragma unroll
    for (int m = 0; m < 9; m++) X[m] *= gate;

    // dense Wd (own parity) + bias + silu gate 2
    dense1(X, kp.Wd + iter * NF * NF, lane, scr);
    if (w == 0) X[0] += kp.bd[iter * NF + lane];
    __syncthreads();
    if (w == 0) sG[lane] = X[0];
    __syncthreads();
    gate = sigm(sG[lane]);
#pragma unroll
    for (int m = 0; m < 9; m++) X[m] *= gate;

    // couple(x, xEF, Wt): stage X and E, compute own out-parity
    float E[9];
    float* xeg = g_xEF + node * XS + w * 288;
#pragma unroll
    for (int m = 0; m < 9; m++) {
        E[m] = xeg[m * NF + lane];
        sStage[w][m * NF + lane] = X[m];       // X0 / X1
        sStage[2 + w][m * NF + lane] = E[m];   // E0 / E1
    }
    __syncthreads();
    float wt[27];
#pragma unroll
    for (int j = 0; j < 27; j++) wt[j] = kp.Wt[(iter * 27 + j) * NF + lane];
    {
        float XA0[9], XA1[9], EP[9], EQ[9];
#pragma unroll
        for (int m = 0; m < 9; m++) {
            XA0[m] = sStage[0][m * NF + lane];
            XA1[m] = sStage[1][m * NF + lane];
            EP[m]  = sStage[2 + w][m * NF + lane];
            EQ[m]  = sStage[3 - w][m * NF + lane];
        }
        float O[9];
        couple1<9>(XA0, XA1, EP, EQ, wt, O);
#pragma unroll
        for (int m = 0; m < 9; m++) {
            xeg[m * NF + lane] = O[m];
            X[m] += O[m];
        }
    }

    // tensor_dense: U = X@Wtd1, V = X@Wtd2 (own parity), couple
    float U[9], V[9];
#pragma unroll
    for (int m = 0; m < 9; m++) { U[m] = X[m]; V[m] = X[m]; }
    dense1(U, kp.Wtd1 + iter * NF * NF, lane, scr);
    dense1(V, kp.Wtd2 + iter * NF * NF, lane, scr);
    __syncthreads();   // previous stage fully consumed
#pragma unroll
    for (int m = 0; m < 9; m++) {
        sStage[w][m * NF + lane] = U[m];       // U0 / U1
        sStage[2 + w][m * NF + lane] = V[m];   // V0 / V1
    }
    __syncthreads();
#pragma unroll
    for (int j = 0; j < 27; j++) wt[j] = kp.Wtdp[(iter * 27 + j) * NF + lane];
    {
        float U0[9], U1[9], VP[9], VQ[9];
#pragma unroll
        for (int m = 0; m < 9; m++) {
            U0[m] = sStage[0][m * NF + lane];
            U1[m] = sStage[1][m * NF + lane];
            VP[m] = sStage[2 + w][m * NF + lane];
            VQ[m] = sStage[3 - w][m * NF + lane];
        }
        float O[9];
        couple1<9>(U0, U1, VP, VQ, wt, O);
#pragma unroll
        for (int m = 0; m < 9; m++) X[m] = O[m] + Y[m];   // final x of this iter
    }

    if constexpr (!RO) {
        float* xo = g_xbuf[inbuf ^ 1] + node * XS + w * 288;
#pragma unroll
        for (int m = 0; m < 9; m++) xo[m * NF + lane] = X[m];
        return;
    } else {
        // ================= slimmed readout =================
        // Only 4 rows of x affect outputs: (p0,m0) -> scal/q/aE and
        // (p1,m1..3) -> dipole. The readout denses mix features, not rows;
        // rows couple only through the scalar silu gate. So warp0 carries the
        // scalar row, warp1 carries the 3 vector rows. Dropped rows never
        // influence any output (bit-identical results).
        float Rr[3];
        if (w == 0) { Rr[0] = X[0]; Rr[1] = 0.0f; Rr[2] = 0.0f; }
        else        { Rr[0] = X[1]; Rr[1] = X[2]; Rr[2] = X[3]; }

#pragma unroll
        for (int i = 0; i < 4; i++) {
            dense3(Rr, kp.Wh + i * NF * NF, lane, scr);
            if (w == 0) Rr[0] += kp.bh[i * NF + lane];
            __syncthreads();
            if (w == 0) sG[lane] = Rr[0];
            __syncthreads();
            float g2 = sigm(sG[lane]);
#pragma unroll
            for (int r = 0; r < 3; r++) Rr[r] *= g2;
        }
        dense3(Rr, kp.Wh + 4 * NF * NF, lane, scr);
        if (w == 0) Rr[0] += kp.bh[4 * NF + lane];

        // dipole denses on xd rows (warp0: scalar row; warp1: 3 vector rows)
        float Ur[3], Vr[3];
#pragma unroll
        for (int r = 0; r < 3; r++) { Ur[r] = Rr[r]; Vr[r] = Rr[r]; }
        dense3(Ur, kp.Wdip1, lane, scr);
        dense3(Vr, kp.Wdip2, lane, scr);

        __syncthreads();
        if (w == 0) {
            sG[lane] = Ur[0];              // U0[0]
            sStage[0][lane] = Vr[0];       // V0[0]
            float scal = Rr[0];
            float q = warp_sum(scal * kp.Wq[lane]);
            float ae = warp_sum(scal * kp.We[lane]);
            if (lane == 0) {
                g_q[node] = q;
                g_aE[node] = ae + kp.be[0] + kp.ebias[kp.Zarr[node]];
            }
        }
        __syncthreads();
        if (w == 1) {
            float U00 = sG[lane];
            float V00 = sStage[0][lane];
            float wd = kp.wdip[lane];
            float d0 = warp_sum(dip_term<1>(U00, V00, Ur, Vr, kp.Wdipp, lane) * wd);
            float d1 = warp_sum(dip_term<2>(U00, V00, Ur, Vr, kp.Wdipp, lane) * wd);
            float d2 = warp_sum(dip_term<3>(U00, V00, Ur, Vr, kp.Wdipp, lane) * wd);
            if (lane == 0) {
                g_dip[node * 3 + 0] = d0;
                g_dip[node * 3 + 1] = d1;
                g_dip[node * 3 + 2] = d2;
            }
        }
    }
}

// ---------------------------------------------------------------------------
// Per-molecule reduction: energy (+Coulomb), dipole
// ---------------------------------------------------------------------------
__global__ void __launch_bounds__(32) reduce_kernel(
    const float* __restrict__ pos,
    const int* __restrict__ dst_idx, const int* __restrict__ src_idx,
    float* __restrict__ out) {
    int mol = blockIdx.x;
    int lane = threadIdx.x;
    int node = mol * NATOM + lane;

    float px = pos[node * 3 + 0], py = pos[node * 3 + 1], pz = pos[node * 3 + 2];
    float cx = warp_sum(px) * (1.0f / 32.0f);
    float cy = warp_sum(py) * (1.0f / 32.0f);
    float cz = warp_sum(pz) * (1.0f / 32.0f);

    float e = warp_sum(g_aE[node]);
    float q = g_q[node];
    float dx = warp_sum(q * (px - cx) + g_dip[node * 3 + 0]);
    float dy = warp_sum(q * (py - cy) + g_dip[node * 3 + 1]);
    float dz = warp_sum(q * (pz - cz) + g_dip[node * 3 + 2]);

    float cacc = 0.0f;
    for (int t = 0; t < 31; t++) {
        int k = t * 32 + lane;
        int e_idx = mol * EPM + k;
        int s = src_idx[k] + mol * NATOM;
        int d = dst_idx[k] + mol * NATOM;
        cacc += g_q[s] * g_q[d] / (g_r[e_idx] + 1e-10f);
    }
    float coul = warp_sum(cacc) * 0.5f;

    if (lane == 0) {
        out[mol] = e + coul * 14.399645f;
        out[NMOL + mol * 3 + 0] = dx;
        out[NMOL + mol * 3 + 1] = dy;
        out[NMOL + mol * 3 + 2] = dz;
    }
}

// ---------------------------------------------------------------------------
// Launch
// ---------------------------------------------------------------------------
extern "C" void kernel_launch(void* const* d_in, const int* in_sizes, int n_in,
                              void* d_out, int out_size) {
    int sft = (n_in >= 24) ? 1 : 0;

    const int*   Zarr   = (const int*)  d_in[0];
    const float* pos    = (const float*)d_in[1];
    const float* Ef     = (const float*)d_in[2];
    const int*   dsti   = (const int*)  d_in[3];
    const int*   srci   = (const int*)  d_in[4];

    KParams kp;
    kp.Wmp    = (const float*)d_in[6 + sft];
    kp.Wd     = (const float*)d_in[7 + sft];
    kp.bd     = (const float*)d_in[8 + sft];
    kp.Wt     = (const float*)d_in[9 + sft];
    kp.Wtd1   = (const float*)d_in[10 + sft];
    kp.Wtd2   = (const float*)d_in[11 + sft];
    kp.Wtdp   = (const float*)d_in[12 + sft];
    kp.Wh     = (const float*)d_in[13 + sft];
    kp.bh     = (const float*)d_in[14 + sft];
    kp.Wq     = (const float*)d_in[15 + sft];
    kp.Wdip1  = (const float*)d_in[16 + sft];
    kp.Wdip2  = (const float*)d_in[17 + sft];
    kp.Wdipp  = (const float*)d_in[18 + sft];
    kp.wdip   = (const float*)d_in[19 + sft];
    kp.We     = (const float*)d_in[20 + sft];
    kp.be     = (const float*)d_in[21 + sft];
    kp.ebias  = (const float*)d_in[22 + sft];
    kp.Zarr   = Zarr;

    const float* embed = (const float*)d_in[5 + sft];
    float* out = (float*)d_out;

    edgeinit_kernel<<<128, 256>>>(pos, dsti, srci, Zarr, embed, Ef);

    msgupd_kernel<2, false><<<NNODE, 64>>>(0, 0, kp);
    msgupd_kernel<2, false><<<NNODE, 64>>>(1, 1, kp);
    msgupd_kernel<0, true><<<NNODE, 64>>>(0, 2, kp);

    reduce_kernel<<<NMOL, 32>>>(pos, dsti, srci, out);
    (void)in_sizes; (void)out_size;
}